// round 2
// baseline (speedup 1.0000x reference)
#include <cuda_runtime.h>
#include <cuda_bf16.h>
#include <cstdint>

// Problem constants
#define N_BATCH 16
#define CD      256        // code dim
#define HWSZ    1024       // 32*32
#define N_PIX   (N_BATCH * HWSZ)   // 16384
#define N_CODE  8192

// Output layout (float32, concatenated): [quantized | st | indices]
#define OFF_ST   (N_BATCH * CD * HWSZ)          // 4194304
#define OFF_IDX  (2 * N_BATCH * CD * HWSZ)      // 8388608

// Scratch (device globals: no allocation allowed)
__device__ float g_zt[N_PIX * CD];     // transposed z: [pixel][c]
__device__ float g_zn2[N_PIX];         // ||z_i||^2  (reference rounding order)
__device__ float g_en2[N_CODE];        // ||emb_j||^2 (reference rounding order)
__device__ int   g_idx[N_PIX];         // argmin indices

// ---------------------------------------------------------------------------
// 1) Transpose z [16][256][1024] -> zt [16384][256]
// ---------------------------------------------------------------------------
__global__ void transpose_z_kernel(const float* __restrict__ z) {
    __shared__ float tile[32][33];
    const int n  = blockIdx.z;
    const int c0 = blockIdx.y * 32;
    const int p0 = blockIdx.x * 32;
    const int tx = threadIdx.x;     // 0..31
    const int ty = threadIdx.y;     // 0..7
#pragma unroll
    for (int i = 0; i < 4; ++i) {
        int c = c0 + ty + i * 8;
        tile[ty + i * 8][tx] = z[((size_t)(n * CD + c)) * HWSZ + p0 + tx];
    }
    __syncthreads();
#pragma unroll
    for (int i = 0; i < 4; ++i) {
        int p = p0 + ty + i * 8;
        g_zt[((size_t)(n * HWSZ + p)) * CD + c0 + tx] = tile[tx][ty + i * 8];
    }
}

// ---------------------------------------------------------------------------
// 2a) ||z_i||^2 with XLA:CPU-style rounding: sequential ascending scalar loop,
//     multiply rounded separately from the add (no FMA contraction).
//     One thread per pixel row of the transposed buffer.
// ---------------------------------------------------------------------------
__global__ void zn2_kernel() {
    const int p = blockIdx.x * blockDim.x + threadIdx.x;
    if (p >= N_PIX) return;
    const float* row = g_zt + (size_t)p * CD;
    float acc = 0.f;
#pragma unroll 8
    for (int k = 0; k < CD; ++k) {
        float v = __ldg(&row[k]);
        acc = __fadd_rn(acc, __fmul_rn(v, v));
    }
    g_zn2[p] = acc;
}

// ---------------------------------------------------------------------------
// 2b) ||emb_j||^2, same sequential rounding semantics. One thread per code.
// ---------------------------------------------------------------------------
__global__ void en2_kernel(const float* __restrict__ emb) {
    const int j = blockIdx.x * blockDim.x + threadIdx.x;
    if (j >= N_CODE) return;
    const float* row = emb + (size_t)j * CD;
    float acc = 0.f;
#pragma unroll 8
    for (int k = 0; k < CD; ++k) {
        float v = __ldg(&row[k]);
        acc = __fadd_rn(acc, __fmul_rn(v, v));
    }
    g_en2[j] = acc;
}

// ---------------------------------------------------------------------------
// 3) Fused distance GEMM + argmin, emulating the reference bit-exactly:
//      m_ij = single-accumulator FMA chain, ascending k (Eigen/cuBLAS order)
//      d    = fl( fl( zz_i - fl(2*m_ij) ) + ee_j )
//      argmin over j, lowest index on ties (jnp.argmin semantics).
//    BM=128 queries per block, all 8192 codes in BN=128 tiles, K=256.
// ---------------------------------------------------------------------------
#define BM 128
#define BN 128
#define BK 8
#define TM 8
#define TN 8

__global__ __launch_bounds__(256)
void dist_argmin_kernel(const float* __restrict__ emb) {
    __shared__ float As[2][BK][BM];
    __shared__ float Bs[2][BK][BN];
    __shared__ float sv[BM][16];
    __shared__ int   si[BM][16];

    const int tid  = threadIdx.x;
    const int tRow = tid >> 4;          // 0..15
    const int tCol = tid & 15;          // 0..15
    const int m0   = blockIdx.x * BM;

    const int lr = tid >> 1;            // loader row 0..127
    const int lc = (tid & 1) * 4;       // loader col 0 or 4

    float bv[TM];
    int   bi[TM];
    float rz[TM];                       // ||z||^2 for my 8 query rows
#pragma unroll
    for (int i = 0; i < TM; ++i) {
        bv[i] = 3.4e38f; bi[i] = 0;
        rz[i] = __ldg(&g_zn2[m0 + tRow * TM + i]);
    }

    const float* Abase = g_zt + (size_t)(m0 + lr) * CD + lc;

    for (int nt = 0; nt < N_CODE / BN; ++nt) {
        const int n0 = nt * BN;
        const float* Bbase = emb + (size_t)(n0 + lr) * CD + lc;

        float acc[TM][TN];
#pragma unroll
        for (int i = 0; i < TM; ++i)
#pragma unroll
            for (int j = 0; j < TN; ++j) acc[i][j] = 0.f;

        // prefetch kt = 0 and stage into buffer 0
        float4 pa = *(const float4*)(Abase);
        float4 pb = *(const float4*)(Bbase);
        As[0][lc + 0][lr] = pa.x; As[0][lc + 1][lr] = pa.y;
        As[0][lc + 2][lr] = pa.z; As[0][lc + 3][lr] = pa.w;
        Bs[0][lc + 0][lr] = pb.x; Bs[0][lc + 1][lr] = pb.y;
        Bs[0][lc + 2][lr] = pb.z; Bs[0][lc + 3][lr] = pb.w;
        __syncthreads();

        int buf = 0;
#pragma unroll 1
        for (int kt = 0; kt < CD / BK; ++kt) {
            if (kt + 1 < CD / BK) {
                pa = *(const float4*)(Abase + (kt + 1) * BK);
                pb = *(const float4*)(Bbase + (kt + 1) * BK);
            }
#pragma unroll
            for (int k = 0; k < BK; ++k) {
                float rm[TM], rn[TN];
                *(float4*)&rm[0] = *(const float4*)&As[buf][k][tRow * TM];
                *(float4*)&rm[4] = *(const float4*)&As[buf][k][tRow * TM + 4];
                *(float4*)&rn[0] = *(const float4*)&Bs[buf][k][tCol * TN];
                *(float4*)&rn[4] = *(const float4*)&Bs[buf][k][tCol * TN + 4];
#pragma unroll
                for (int i = 0; i < TM; ++i)
#pragma unroll
                    for (int j = 0; j < TN; ++j)
                        acc[i][j] = fmaf(rm[i], rn[j], acc[i][j]);
            }
            if (kt + 1 < CD / BK) {
                int nb = buf ^ 1;
                As[nb][lc + 0][lr] = pa.x; As[nb][lc + 1][lr] = pa.y;
                As[nb][lc + 2][lr] = pa.z; As[nb][lc + 3][lr] = pa.w;
                Bs[nb][lc + 0][lr] = pb.x; Bs[nb][lc + 1][lr] = pb.y;
                Bs[nb][lc + 2][lr] = pb.z; Bs[nb][lc + 3][lr] = pb.w;
                __syncthreads();
                buf = nb;
            }
        }

        // epilogue: reference rounding chain, running argmin.
        // ascending code order within a thread -> strict < keeps first min.
#pragma unroll
        for (int j = 0; j < TN; ++j) {
            int code = n0 + tCol * TN + j;
            float e2 = __ldg(&g_en2[code]);
#pragma unroll
            for (int i = 0; i < TM; ++i) {
                float t  = __fmul_rn(2.0f, acc[i][j]);     // fl(2*m), exact
                float s1 = __fadd_rn(rz[i], -t);           // fl(zz - 2m): absorption
                float s  = __fadd_rn(s1, e2);              // fl(... + ee)
                if (s < bv[i]) { bv[i] = s; bi[i] = code; }
            }
        }
        __syncthreads();   // smem buffers reused next nt
    }

    // cross-thread reduction over the 16 column-threads per query row;
    // exact ties -> lowest code index (jnp.argmin first-occurrence).
#pragma unroll
    for (int i = 0; i < TM; ++i) {
        sv[tRow * TM + i][tCol] = bv[i];
        si[tRow * TM + i][tCol] = bi[i];
    }
    __syncthreads();
    if (tid < BM) {
        float best = sv[tid][0];
        int   bidx = si[tid][0];
#pragma unroll
        for (int c = 1; c < 16; ++c) {
            float v  = sv[tid][c];
            int   ix = si[tid][c];
            if (v < best || (v == best && ix < bidx)) { best = v; bidx = ix; }
        }
        g_idx[m0 + tid] = bidx;
    }
}

// ---------------------------------------------------------------------------
// 4) Gather: quantized[n][c][hw] = emb[idx][c]; st = fl(z + fl(q - z))
//    (matches reference straight-through rounding); indices as float.
// ---------------------------------------------------------------------------
__global__ __launch_bounds__(256)
void gather_kernel(const float* __restrict__ z, const float* __restrict__ emb,
                   float* __restrict__ out) {
    const int tx = threadIdx.x & 31;
    const int ty = threadIdx.x >> 5;       // 0..7
    const int p  = blockIdx.x * 32 + tx;
    const int idx = g_idx[p];
    const int n  = p >> 10;
    const int hw = p & 1023;
    const size_t base = (size_t)n * (CD * HWSZ) + hw;
    const float* erow = emb + (size_t)idx * CD;
#pragma unroll
    for (int cc = 0; cc < CD / 8; ++cc) {
        int c = cc * 8 + ty;
        float q = __ldg(&erow[c]);
        size_t off = base + (size_t)c * HWSZ;
        out[off] = q;
        float zv = z[off];
        out[OFF_ST + off] = __fadd_rn(zv, __fadd_rn(q, -zv));
    }
    if (ty == 0) out[OFF_IDX + p] = (float)idx;
}

// ---------------------------------------------------------------------------
extern "C" void kernel_launch(void* const* d_in, const int* in_sizes, int n_in,
                              void* d_out, int out_size) {
    const float* z   = (const float*)d_in[0];   // (16,256,32,32)
    const float* emb = (const float*)d_in[1];   // (8192,256)
    float* out = (float*)d_out;

    transpose_z_kernel<<<dim3(32, 8, 16), dim3(32, 8)>>>(z);
    zn2_kernel<<<N_PIX / 256, 256>>>();
    en2_kernel<<<N_CODE / 256, 256>>>(emb);
    dist_argmin_kernel<<<N_PIX / BM, 256>>>(emb);
    gather_kernel<<<N_PIX / 32, 256>>>(z, emb, out);
}

// round 6
// speedup vs baseline: 4.9804x; 4.9804x over previous
#include <cuda_runtime.h>
#include <cuda_bf16.h>
#include <cstdint>

// Problem constants
#define N_BATCH 16
#define CD      256
#define HWSZ    1024
#define N_PIX   (N_BATCH * HWSZ)   // 16384
#define N_CODE  8192

#define OFF_ST   (N_BATCH * CD * HWSZ)
#define OFF_IDX  (2 * N_BATCH * CD * HWSZ)

#define MAXC        256
#define CAND_MARGIN 6.0e-4f
#define RESC_MARGIN 4.0e-4f

// Scratch (device globals; no allocation allowed)
__device__ float          g_zt[N_PIX * CD];    // transposed z fp32 (exact rescue)
__device__ __nv_bfloat16  g_abf[N_PIX * CD];   // bf16 A
__device__ __nv_bfloat16  g_bbf[N_CODE * CD];  // bf16 B
__device__ float          g_zn2[N_PIX];
__device__ float          g_en2[N_CODE];
__device__ int            g_ccount[N_PIX];
__device__ float          g_cs[N_PIX * MAXC];
__device__ int            g_ci[N_PIX * MAXC];
__device__ int            g_idx[N_PIX];

// ---------------- helpers ----------------
__device__ __forceinline__ uint32_t smem_u32(const void* p) {
    uint32_t a;
    asm("{ .reg .u64 t; cvta.to.shared.u64 t, %1; cvt.u32.u64 %0, t; }" : "=r"(a) : "l"(p));
    return a;
}
__device__ __forceinline__ void cp16(uint32_t dst, const void* src) {
    asm volatile("cp.async.cg.shared.global [%0], [%1], 16;"
                 :: "r"(dst), "l"(__cvta_generic_to_global(src)));
}
__device__ __forceinline__ void cp_commit() { asm volatile("cp.async.commit_group;"); }
__device__ __forceinline__ void cp_wait0()  { asm volatile("cp.async.wait_group 0;"); }

__device__ __forceinline__ float score_chain(float zz, float m, float ee) {
    return __fadd_rn(__fadd_rn(zz, -__fmul_rn(2.0f, m)), ee);
}

// ---------------- prep kernels ----------------
__global__ void transpose_z_kernel(const float* __restrict__ z) {
    __shared__ float tile[32][33];
    const int n = blockIdx.z, c0 = blockIdx.y * 32, p0 = blockIdx.x * 32;
    const int tx = threadIdx.x, ty = threadIdx.y;
#pragma unroll
    for (int i = 0; i < 4; ++i) {
        int c = c0 + ty + i * 8;
        tile[ty + i * 8][tx] = z[((size_t)(n * CD + c)) * HWSZ + p0 + tx];
    }
    __syncthreads();
#pragma unroll
    for (int i = 0; i < 4; ++i) {
        int p = p0 + ty + i * 8;
        size_t idx = ((size_t)(n * HWSZ + p)) * CD + c0 + tx;
        float v = tile[tx][ty + i * 8];
        g_zt[idx]  = v;
        g_abf[idx] = __float2bfloat16(v);
    }
}

__global__ void zero_counts_kernel() {
    int i = blockIdx.x * blockDim.x + threadIdx.x;
    if (i < N_PIX) g_ccount[i] = 0;
}

__global__ void zn2_kernel() {
    const int p = blockIdx.x * blockDim.x + threadIdx.x;
    if (p >= N_PIX) return;
    const float* row = g_zt + (size_t)p * CD;
    float acc = 0.f;
#pragma unroll 8
    for (int k = 0; k < CD; ++k) { float v = __ldg(&row[k]); acc = __fadd_rn(acc, __fmul_rn(v, v)); }
    g_zn2[p] = acc;
}

__global__ void en2_kernel(const float* __restrict__ emb) {
    const int j = blockIdx.x * blockDim.x + threadIdx.x;
    if (j >= N_CODE) return;
    const float* row = emb + (size_t)j * CD;
    float acc = 0.f;
#pragma unroll 8
    for (int k = 0; k < CD; ++k) { float v = __ldg(&row[k]); acc = __fadd_rn(acc, __fmul_rn(v, v)); }
    g_en2[j] = acc;
}

__global__ void convert_b_kernel(const float* __restrict__ emb) {
    const int j = blockIdx.x, k = threadIdx.x;
    g_bbf[(size_t)j * CD + k] = __float2bfloat16(emb[(size_t)j * CD + k]);
}

// ---------------- GEMM (mma.sync bf16) + candidate collection ----------------
// CTA: M=128 queries x N-group=1024 codes (8 blocks of 128), K=256.
// 8 warps in 2(M)x4(N); warp tile 64x32 via m16n8k16.
#define SMA_STRIDE 264
#define SMB_STRIDE 72
#define SM_A       0
#define SM_B0      (128 * SMA_STRIDE * 2)            // 67584
#define SM_BSZ     (128 * SMB_STRIDE * 2)            // 18432
#define SM_B1      (SM_B0 + SM_BSZ)
#define SM_RMIN    (SM_B1 + SM_BSZ)                  // 104448
#define SMEM_TOTAL (SM_RMIN + 512)                   // 104960

__global__ __launch_bounds__(256, 2)
void gemm_cand_kernel() {
    extern __shared__ char smem[];
    const uint32_t sb = smem_u32(smem);
    const int tid = threadIdx.x, lane = tid & 31, warp = tid >> 5;
    const int warpM = warp >> 2;        // 0..1
    const int warpN = warp & 3;         // 0..3
    const int m0 = blockIdx.y * 128;
    const int g0 = blockIdx.x * 1024;
    unsigned* rowminU = (unsigned*)(smem + SM_RMIN);

    // stage A once: 128 rows x 512 bytes = 4096 x 16B
    {
        const __nv_bfloat16* Ab = g_abf + (size_t)m0 * CD;
#pragma unroll
        for (int i = 0; i < 16; ++i) {
            int g = i * 256 + tid, row = g >> 5, grp = g & 31;
            cp16(sb + SM_A + row * (SMA_STRIDE * 2) + grp * 16, Ab + (size_t)row * CD + grp * 8);
        }
        cp_commit();
    }
    if (tid < 128) rowminU[tid] = 0x7F7FFFFFu;

    float zz0[4], zz1[4];
#pragma unroll
    for (int ti = 0; ti < 4; ++ti) {
        int r = m0 + warpM * 64 + ti * 16 + (lane >> 2);
        zz0[ti] = __ldg(&g_zn2[r]);
        zz1[ti] = __ldg(&g_zn2[r + 8]);
    }

    // ldmatrix per-lane bases
    const uint32_t aAddrBase = sb + SM_A + (warpM * 64 + (lane & 15)) * (SMA_STRIDE * 2) + (lane >> 4) * 16;
    const uint32_t bRowOff   = (warpN * 32 + (lane & 7)) * (SMB_STRIDE * 2) + ((lane >> 3) & 1) * 16;

    for (int nb = 0; nb < 8; ++nb) {
        const int n0 = g0 + nb * 128;
        float c[4][4][4];
#pragma unroll
        for (int ti = 0; ti < 4; ++ti)
#pragma unroll
            for (int tj = 0; tj < 4; ++tj)
#pragma unroll
                for (int d = 0; d < 4; ++d) c[ti][tj][d] = 0.f;

        // B chunk = [128 rows][64 halves] = 128 B/row -> 8 x 16B groups/row
        // -> 1024 cp16 per chunk = 4 iters x 256 threads.  (R5 bug: was 512.)
        auto loadB = [&](int kc, int buf) {
            const __nv_bfloat16* Bb = g_bbf + (size_t)n0 * CD + kc * 64;
            uint32_t dst = sb + (buf ? SM_B1 : SM_B0);
#pragma unroll
            for (int i = 0; i < 4; ++i) {
                int g = i * 256 + tid, row = g >> 3, grp = g & 7;
                cp16(dst + row * (SMB_STRIDE * 2) + grp * 16, Bb + (size_t)row * CD + grp * 8);
            }
            cp_commit();
        };
        loadB(0, 0);

#pragma unroll 1
        for (int kc = 0; kc < 4; ++kc) {
            const int buf = kc & 1;
            cp_wait0();
            __syncthreads();
            if (kc < 3) loadB(kc + 1, buf ^ 1);
            const uint32_t bBase = sb + (buf ? SM_B1 : SM_B0) + bRowOff;
#pragma unroll
            for (int ks = 0; ks < 4; ++ks) {
                uint32_t a[4][4], b[4][2];
#pragma unroll
                for (int ti = 0; ti < 4; ++ti) {
                    uint32_t ad = aAddrBase + ti * 16 * (SMA_STRIDE * 2) + (kc * 64 + ks * 16) * 2;
                    asm volatile("ldmatrix.sync.aligned.m8n8.x4.shared.b16 {%0,%1,%2,%3}, [%4];"
                                 : "=r"(a[ti][0]), "=r"(a[ti][1]), "=r"(a[ti][2]), "=r"(a[ti][3])
                                 : "r"(ad));
                }
#pragma unroll
                for (int tj = 0; tj < 4; ++tj) {
                    uint32_t bd = bBase + tj * 8 * (SMB_STRIDE * 2) + (ks * 16) * 2;
                    asm volatile("ldmatrix.sync.aligned.m8n8.x2.shared.b16 {%0,%1}, [%2];"
                                 : "=r"(b[tj][0]), "=r"(b[tj][1]) : "r"(bd));
                }
#pragma unroll
                for (int ti = 0; ti < 4; ++ti)
#pragma unroll
                    for (int tj = 0; tj < 4; ++tj)
                        asm volatile(
                            "mma.sync.aligned.m16n8k16.row.col.f32.bf16.bf16.f32 "
                            "{%0,%1,%2,%3}, {%4,%5,%6,%7}, {%8,%9}, {%0,%1,%2,%3};"
                            : "+f"(c[ti][tj][0]), "+f"(c[ti][tj][1]),
                              "+f"(c[ti][tj][2]), "+f"(c[ti][tj][3])
                            : "r"(a[ti][0]), "r"(a[ti][1]), "r"(a[ti][2]), "r"(a[ti][3]),
                              "r"(b[tj][0]), "r"(b[tj][1]));
            }
        }

        // epilogue: scores, running row-min, candidate collection
        float ee0[4], ee1[4];
#pragma unroll
        for (int tj = 0; tj < 4; ++tj) {
            int cidx = n0 + warpN * 32 + tj * 8 + 2 * (lane & 3);
            ee0[tj] = __ldg(&g_en2[cidx]);
            ee1[tj] = __ldg(&g_en2[cidx + 1]);
        }
#pragma unroll
        for (int ti = 0; ti < 4; ++ti) {
            float mn0 = 3.4e38f, mn1 = 3.4e38f;
#pragma unroll
            for (int tj = 0; tj < 4; ++tj) {
                float s0 = score_chain(zz0[ti], c[ti][tj][0], ee0[tj]);
                float s1 = score_chain(zz0[ti], c[ti][tj][1], ee1[tj]);
                float s2 = score_chain(zz1[ti], c[ti][tj][2], ee0[tj]);
                float s3 = score_chain(zz1[ti], c[ti][tj][3], ee1[tj]);
                c[ti][tj][0] = s0; c[ti][tj][1] = s1; c[ti][tj][2] = s2; c[ti][tj][3] = s3;
                mn0 = fminf(mn0, fminf(s0, s1));
                mn1 = fminf(mn1, fminf(s2, s3));
            }
            int r0 = warpM * 64 + ti * 16 + (lane >> 2);
            atomicMin(&rowminU[r0],     __float_as_uint(mn0));
            atomicMin(&rowminU[r0 + 8], __float_as_uint(mn1));
        }
        __syncthreads();
#pragma unroll
        for (int ti = 0; ti < 4; ++ti) {
            int r0 = warpM * 64 + ti * 16 + (lane >> 2);
            float t0 = __uint_as_float(rowminU[r0])     + CAND_MARGIN;
            float t1 = __uint_as_float(rowminU[r0 + 8]) + CAND_MARGIN;
            int q0 = m0 + r0, q1 = q0 + 8;
#pragma unroll
            for (int tj = 0; tj < 4; ++tj) {
                int cb = n0 + warpN * 32 + tj * 8 + 2 * (lane & 3);
                if (c[ti][tj][0] <= t0) {
                    int pos = atomicAdd(&g_ccount[q0], 1);
                    if (pos < MAXC) { g_cs[(size_t)q0 * MAXC + pos] = c[ti][tj][0]; g_ci[(size_t)q0 * MAXC + pos] = cb; }
                }
                if (c[ti][tj][1] <= t0) {
                    int pos = atomicAdd(&g_ccount[q0], 1);
                    if (pos < MAXC) { g_cs[(size_t)q0 * MAXC + pos] = c[ti][tj][1]; g_ci[(size_t)q0 * MAXC + pos] = cb + 1; }
                }
                if (c[ti][tj][2] <= t1) {
                    int pos = atomicAdd(&g_ccount[q1], 1);
                    if (pos < MAXC) { g_cs[(size_t)q1 * MAXC + pos] = c[ti][tj][2]; g_ci[(size_t)q1 * MAXC + pos] = cb; }
                }
                if (c[ti][tj][3] <= t1) {
                    int pos = atomicAdd(&g_ccount[q1], 1);
                    if (pos < MAXC) { g_cs[(size_t)q1 * MAXC + pos] = c[ti][tj][3]; g_ci[(size_t)q1 * MAXC + pos] = cb + 1; }
                }
            }
        }
        __syncthreads();
    }
}

// ---------------- rescue: exact fp32 chain on tiny candidate set ----------------
__device__ __forceinline__ float exact_score(int q, int code, const float* __restrict__ emb,
                                             float zz, float ee) {
    const float* zr = g_zt + (size_t)q * CD;
    const float* er = emb + (size_t)code * CD;
    float acc = 0.f;
#pragma unroll 8
    for (int k = 0; k < CD; ++k) acc = fmaf(__ldg(&zr[k]), __ldg(&er[k]), acc);
    return __fadd_rn(__fadd_rn(zz, -__fmul_rn(2.0f, acc)), ee);
}

__global__ __launch_bounds__(256)
void rescue_kernel(const float* __restrict__ emb) {
    const int q = (blockIdx.x * blockDim.x + threadIdx.x) >> 5;
    const int lane = threadIdx.x & 31;
    if (q >= N_PIX) return;
    const int cnt = g_ccount[q];
    const float zz = __ldg(&g_zn2[q]);
    unsigned long long best = 0xFFFFFFFFFFFFFFFFull;

    if (cnt <= MAXC) {
        unsigned long long abest = 0xFFFFFFFFFFFFFFFFull;
        for (int base = 0; base < cnt; base += 32) {
            int i = base + lane;
            if (i < cnt) {
                float s = g_cs[(size_t)q * MAXC + i];
                unsigned long long k =
                    ((unsigned long long)__float_as_uint(s) << 32) | (unsigned)g_ci[(size_t)q * MAXC + i];
                abest = min(abest, k);
            }
        }
#pragma unroll
        for (int o = 16; o; o >>= 1) abest = min(abest, __shfl_xor_sync(0xFFFFFFFFu, abest, o));
        const float thr = __uint_as_float((uint32_t)(abest >> 32)) + RESC_MARGIN;
        for (int base = 0; base < cnt; base += 32) {
            int i = base + lane;
            if (i < cnt && g_cs[(size_t)q * MAXC + i] <= thr) {
                int code = g_ci[(size_t)q * MAXC + i];
                float d = exact_score(q, code, emb, zz, __ldg(&g_en2[code]));
                unsigned long long k = ((unsigned long long)__float_as_uint(d) << 32) | (unsigned)code;
                best = min(best, k);
            }
        }
    } else {
        for (int j = lane; j < N_CODE; j += 32) {
            float d = exact_score(q, j, emb, zz, __ldg(&g_en2[j]));
            unsigned long long k = ((unsigned long long)__float_as_uint(d) << 32) | (unsigned)j;
            best = min(best, k);
        }
    }
#pragma unroll
    for (int o = 16; o; o >>= 1) best = min(best, __shfl_xor_sync(0xFFFFFFFFu, best, o));
    if (lane == 0) g_idx[q] = (int)(best & 0xFFFFFFFFull);
}

// ---------------- gather ----------------
__global__ __launch_bounds__(256)
void gather_kernel(const float* __restrict__ z, const float* __restrict__ emb,
                   float* __restrict__ out) {
    const int tx = threadIdx.x & 31;
    const int ty = threadIdx.x >> 5;
    const int p  = blockIdx.x * 32 + tx;
    const int idx = g_idx[p];
    const int n  = p >> 10;
    const int hw = p & 1023;
    const size_t base = (size_t)n * (CD * HWSZ) + hw;
    const float* erow = emb + (size_t)idx * CD;
#pragma unroll
    for (int cc = 0; cc < CD / 8; ++cc) {
        int c = cc * 8 + ty;
        float qv = __ldg(&erow[c]);
        size_t off = base + (size_t)c * HWSZ;
        out[off] = qv;
        float zv = z[off];
        out[OFF_ST + off] = __fadd_rn(zv, __fadd_rn(qv, -zv));
    }
    if (ty == 0) out[OFF_IDX + p] = (float)idx;
}

// ---------------------------------------------------------------------------
extern "C" void kernel_launch(void* const* d_in, const int* in_sizes, int n_in,
                              void* d_out, int out_size) {
    const float* z   = (const float*)d_in[0];
    const float* emb = (const float*)d_in[1];
    float* out = (float*)d_out;

    cudaFuncSetAttribute(gemm_cand_kernel, cudaFuncAttributeMaxDynamicSharedMemorySize, SMEM_TOTAL);

    transpose_z_kernel<<<dim3(32, 8, 16), dim3(32, 8)>>>(z);
    zero_counts_kernel<<<N_PIX / 256, 256>>>();
    zn2_kernel<<<N_PIX / 256, 256>>>();
    en2_kernel<<<N_CODE / 256, 256>>>(emb);
    convert_b_kernel<<<N_CODE, 256>>>(emb);
    gemm_cand_kernel<<<dim3(N_CODE / 1024, N_PIX / 128), 256, SMEM_TOTAL>>>();
    rescue_kernel<<<(N_PIX * 32) / 256, 256>>>(emb);
    gather_kernel<<<N_PIX / 32, 256>>>(z, emb, out);
}

// round 7
// speedup vs baseline: 5.4582x; 1.0959x over previous
#include <cuda_runtime.h>
#include <cuda_bf16.h>
#include <cstdint>

// Problem constants
#define N_BATCH 16
#define CD      256
#define HWSZ    1024
#define N_PIX   (N_BATCH * HWSZ)   // 16384
#define N_CODE  8192

#define OFF_ST   (N_BATCH * CD * HWSZ)
#define OFF_IDX  (2 * N_BATCH * CD * HWSZ)

#define MAXC        256
#define CAND_MARGIN 6.0e-4f
#define RESC_MARGIN 4.0e-4f

// Scratch (device globals; no allocation allowed)
__device__ float          g_zt[N_PIX * CD];    // transposed z fp32 (exact rescue)
__device__ __nv_bfloat16  g_abf[N_PIX * CD];   // bf16 A
__device__ __nv_bfloat16  g_bbf[N_CODE * CD];  // bf16 B
__device__ float          g_zn2[N_PIX];
__device__ float          g_en2[N_CODE];
__device__ int            g_ccount[N_PIX];
__device__ float          g_cs[N_PIX * MAXC];
__device__ int            g_ci[N_PIX * MAXC];
__device__ int            g_idx[N_PIX];

// ---------------- helpers ----------------
__device__ __forceinline__ uint32_t smem_u32(const void* p) {
    uint32_t a;
    asm("{ .reg .u64 t; cvta.to.shared.u64 t, %1; cvt.u32.u64 %0, t; }" : "=r"(a) : "l"(p));
    return a;
}
__device__ __forceinline__ void cp16(uint32_t dst, const void* src) {
    asm volatile("cp.async.cg.shared.global [%0], [%1], 16;"
                 :: "r"(dst), "l"(__cvta_generic_to_global(src)));
}
__device__ __forceinline__ void cp_commit() { asm volatile("cp.async.commit_group;"); }
__device__ __forceinline__ void cp_wait0()  { asm volatile("cp.async.wait_group 0;"); }

__device__ __forceinline__ float score_chain(float zz, float m, float ee) {
    return __fadd_rn(__fadd_rn(zz, -__fmul_rn(2.0f, m)), ee);
}

// ---------------- prep: transpose + bf16 A ----------------
__global__ void transpose_z_kernel(const float* __restrict__ z) {
    __shared__ float tile[32][33];
    const int n = blockIdx.z, c0 = blockIdx.y * 32, p0 = blockIdx.x * 32;
    const int tx = threadIdx.x, ty = threadIdx.y;
#pragma unroll
    for (int i = 0; i < 4; ++i) {
        int c = c0 + ty + i * 8;
        tile[ty + i * 8][tx] = z[((size_t)(n * CD + c)) * HWSZ + p0 + tx];
    }
    __syncthreads();
#pragma unroll
    for (int i = 0; i < 4; ++i) {
        int p = p0 + ty + i * 8;
        size_t idx = ((size_t)(n * HWSZ + p)) * CD + c0 + tx;
        float v = tile[tx][ty + i * 8];
        g_zt[idx]  = v;
        g_abf[idx] = __float2bfloat16(v);
    }
}

// ---------------- prep: fused norms (+ B convert + count zero) -------------
// One 64-thread block per row. Rows [0,N_PIX) = zn2 (from g_zt);
// rows [N_PIX, N_PIX+N_CODE) = en2 (from emb) + bf16 B conversion.
// Lane 0 runs the bit-exact sequential fadd(acc, fmul(v,v)) chain from smem.
__global__ __launch_bounds__(64)
void norms_kernel(const float* __restrict__ emb) {
    __shared__ float buf[CD];
    const int r = blockIdx.x;
    const int tid = threadIdx.x;

    if (r < N_PIX) {
        const float4* src = (const float4*)(g_zt + (size_t)r * CD);
        ((float4*)buf)[tid] = __ldg(&src[tid]);
        if (tid == 0) g_ccount[r] = 0;
        __syncthreads();
        if (tid == 0) {
            float acc = 0.f;
#pragma unroll 16
            for (int k = 0; k < CD; ++k) {
                float v = buf[k];
                acc = __fadd_rn(acc, __fmul_rn(v, v));
            }
            g_zn2[r] = acc;
        }
    } else {
        const int j = r - N_PIX;
        const float4* src = (const float4*)(emb + (size_t)j * CD);
        float4 v = __ldg(&src[tid]);
        ((float4*)buf)[tid] = v;
        __nv_bfloat162* dst = (__nv_bfloat162*)(g_bbf + (size_t)j * CD);
        dst[tid * 2]     = __floats2bfloat162_rn(v.x, v.y);
        dst[tid * 2 + 1] = __floats2bfloat162_rn(v.z, v.w);
        __syncthreads();
        if (tid == 0) {
            float acc = 0.f;
#pragma unroll 16
            for (int k = 0; k < CD; ++k) {
                float w = buf[k];
                acc = __fadd_rn(acc, __fmul_rn(w, w));
            }
            g_en2[j] = acc;
        }
    }
}

// ---------------- GEMM (mma.sync bf16) + candidate collection ----------------
// CTA: M=128 queries x N-group=1024 codes (8 blocks of 128), K=256.
// 8 warps in 2(M)x4(N); warp tile 64x32 via m16n8k16.
#define SMA_STRIDE 264
#define SMB_STRIDE 72
#define SM_A       0
#define SM_B0      (128 * SMA_STRIDE * 2)            // 67584
#define SM_BSZ     (128 * SMB_STRIDE * 2)            // 18432
#define SM_B1      (SM_B0 + SM_BSZ)
#define SM_RMIN    (SM_B1 + SM_BSZ)                  // 104448
#define SMEM_TOTAL (SM_RMIN + 512)                   // 104960

__global__ __launch_bounds__(256, 2)
void gemm_cand_kernel() {
    extern __shared__ char smem[];
    const uint32_t sb = smem_u32(smem);
    const int tid = threadIdx.x, lane = tid & 31, warp = tid >> 5;
    const int warpM = warp >> 2;        // 0..1
    const int warpN = warp & 3;         // 0..3
    const int m0 = blockIdx.y * 128;
    const int g0 = blockIdx.x * 1024;
    unsigned* rowminU = (unsigned*)(smem + SM_RMIN);

    // stage A once: 128 rows x 512 bytes = 4096 x 16B
    {
        const __nv_bfloat16* Ab = g_abf + (size_t)m0 * CD;
#pragma unroll
        for (int i = 0; i < 16; ++i) {
            int g = i * 256 + tid, row = g >> 5, grp = g & 31;
            cp16(sb + SM_A + row * (SMA_STRIDE * 2) + grp * 16, Ab + (size_t)row * CD + grp * 8);
        }
        cp_commit();
    }
    if (tid < 128) rowminU[tid] = 0x7F7FFFFFu;

    float zz0[4], zz1[4];
#pragma unroll
    for (int ti = 0; ti < 4; ++ti) {
        int r = m0 + warpM * 64 + ti * 16 + (lane >> 2);
        zz0[ti] = __ldg(&g_zn2[r]);
        zz1[ti] = __ldg(&g_zn2[r + 8]);
    }

    // B chunk loader: [128 rows][64 halves] = 8 x 16B groups/row -> 1024 cp16
    auto loadB = [&](int nbase, int kc, int buf) {
        const __nv_bfloat16* Bb = g_bbf + (size_t)nbase * CD + kc * 64;
        uint32_t dst = sb + (buf ? SM_B1 : SM_B0);
#pragma unroll
        for (int i = 0; i < 4; ++i) {
            int g = i * 256 + tid, row = g >> 3, grp = g & 7;
            cp16(dst + row * (SMB_STRIDE * 2) + grp * 16, Bb + (size_t)row * CD + grp * 8);
        }
        cp_commit();
    };

    // ldmatrix per-lane bases
    const uint32_t aAddrBase = sb + SM_A + (warpM * 64 + (lane & 15)) * (SMA_STRIDE * 2) + (lane >> 4) * 16;
    const uint32_t bRowOff   = (warpN * 32 + (lane & 7)) * (SMB_STRIDE * 2) + ((lane >> 3) & 1) * 16;

    loadB(g0, 0, 0);   // first chunk of first n-block

    for (int nb = 0; nb < 8; ++nb) {
        const int n0 = g0 + nb * 128;
        float c[4][4][4];
#pragma unroll
        for (int ti = 0; ti < 4; ++ti)
#pragma unroll
            for (int tj = 0; tj < 4; ++tj)
#pragma unroll
                for (int d = 0; d < 4; ++d) c[ti][tj][d] = 0.f;

#pragma unroll 1
        for (int kc = 0; kc < 4; ++kc) {
            const int buf = kc & 1;
            cp_wait0();
            __syncthreads();
            if (kc < 3)      loadB(n0, kc + 1, buf ^ 1);
            else if (nb < 7) loadB(n0 + 128, 0, 0);   // prefetch next nb over epilogue
            const uint32_t bBase = sb + (buf ? SM_B1 : SM_B0) + bRowOff;
#pragma unroll
            for (int ks = 0; ks < 4; ++ks) {
                uint32_t a[4][4], b[4][2];
#pragma unroll
                for (int ti = 0; ti < 4; ++ti) {
                    uint32_t ad = aAddrBase + ti * 16 * (SMA_STRIDE * 2) + (kc * 64 + ks * 16) * 2;
                    asm volatile("ldmatrix.sync.aligned.m8n8.x4.shared.b16 {%0,%1,%2,%3}, [%4];"
                                 : "=r"(a[ti][0]), "=r"(a[ti][1]), "=r"(a[ti][2]), "=r"(a[ti][3])
                                 : "r"(ad));
                }
#pragma unroll
                for (int tj = 0; tj < 4; ++tj) {
                    uint32_t bd = bBase + tj * 8 * (SMB_STRIDE * 2) + (ks * 16) * 2;
                    asm volatile("ldmatrix.sync.aligned.m8n8.x2.shared.b16 {%0,%1}, [%2];"
                                 : "=r"(b[tj][0]), "=r"(b[tj][1]) : "r"(bd));
                }
#pragma unroll
                for (int ti = 0; ti < 4; ++ti)
#pragma unroll
                    for (int tj = 0; tj < 4; ++tj)
                        asm volatile(
                            "mma.sync.aligned.m16n8k16.row.col.f32.bf16.bf16.f32 "
                            "{%0,%1,%2,%3}, {%4,%5,%6,%7}, {%8,%9}, {%0,%1,%2,%3};"
                            : "+f"(c[ti][tj][0]), "+f"(c[ti][tj][1]),
                              "+f"(c[ti][tj][2]), "+f"(c[ti][tj][3])
                            : "r"(a[ti][0]), "r"(a[ti][1]), "r"(a[ti][2]), "r"(a[ti][3]),
                              "r"(b[tj][0]), "r"(b[tj][1]));
            }
        }

        // epilogue: scores, running row-min, candidate collection
        float ee0[4], ee1[4];
#pragma unroll
        for (int tj = 0; tj < 4; ++tj) {
            int cidx = n0 + warpN * 32 + tj * 8 + 2 * (lane & 3);
            ee0[tj] = __ldg(&g_en2[cidx]);
            ee1[tj] = __ldg(&g_en2[cidx + 1]);
        }
#pragma unroll
        for (int ti = 0; ti < 4; ++ti) {
            float mn0 = 3.4e38f, mn1 = 3.4e38f;
#pragma unroll
            for (int tj = 0; tj < 4; ++tj) {
                float s0 = score_chain(zz0[ti], c[ti][tj][0], ee0[tj]);
                float s1 = score_chain(zz0[ti], c[ti][tj][1], ee1[tj]);
                float s2 = score_chain(zz1[ti], c[ti][tj][2], ee0[tj]);
                float s3 = score_chain(zz1[ti], c[ti][tj][3], ee1[tj]);
                c[ti][tj][0] = s0; c[ti][tj][1] = s1; c[ti][tj][2] = s2; c[ti][tj][3] = s3;
                mn0 = fminf(mn0, fminf(s0, s1));
                mn1 = fminf(mn1, fminf(s2, s3));
            }
            int r0 = warpM * 64 + ti * 16 + (lane >> 2);
            atomicMin(&rowminU[r0],     __float_as_uint(mn0));
            atomicMin(&rowminU[r0 + 8], __float_as_uint(mn1));
        }
        __syncthreads();
#pragma unroll
        for (int ti = 0; ti < 4; ++ti) {
            int r0 = warpM * 64 + ti * 16 + (lane >> 2);
            float t0 = __uint_as_float(rowminU[r0])     + CAND_MARGIN;
            float t1 = __uint_as_float(rowminU[r0 + 8]) + CAND_MARGIN;
            int q0 = m0 + r0, q1 = q0 + 8;
#pragma unroll
            for (int tj = 0; tj < 4; ++tj) {
                int cb = n0 + warpN * 32 + tj * 8 + 2 * (lane & 3);
                if (c[ti][tj][0] <= t0) {
                    int pos = atomicAdd(&g_ccount[q0], 1);
                    if (pos < MAXC) { g_cs[(size_t)q0 * MAXC + pos] = c[ti][tj][0]; g_ci[(size_t)q0 * MAXC + pos] = cb; }
                }
                if (c[ti][tj][1] <= t0) {
                    int pos = atomicAdd(&g_ccount[q0], 1);
                    if (pos < MAXC) { g_cs[(size_t)q0 * MAXC + pos] = c[ti][tj][1]; g_ci[(size_t)q0 * MAXC + pos] = cb + 1; }
                }
                if (c[ti][tj][2] <= t1) {
                    int pos = atomicAdd(&g_ccount[q1], 1);
                    if (pos < MAXC) { g_cs[(size_t)q1 * MAXC + pos] = c[ti][tj][2]; g_ci[(size_t)q1 * MAXC + pos] = cb; }
                }
                if (c[ti][tj][3] <= t1) {
                    int pos = atomicAdd(&g_ccount[q1], 1);
                    if (pos < MAXC) { g_cs[(size_t)q1 * MAXC + pos] = c[ti][tj][3]; g_ci[(size_t)q1 * MAXC + pos] = cb + 1; }
                }
            }
        }
        __syncthreads();
    }
}

// ---------------- rescue: exact fp32 chain on tiny candidate set ----------------
__device__ __forceinline__ float exact_score(int q, int code, const float* __restrict__ emb,
                                             float zz, float ee) {
    const float* zr = g_zt + (size_t)q * CD;
    const float* er = emb + (size_t)code * CD;
    float acc = 0.f;
#pragma unroll 8
    for (int k = 0; k < CD; ++k) acc = fmaf(__ldg(&zr[k]), __ldg(&er[k]), acc);
    return __fadd_rn(__fadd_rn(zz, -__fmul_rn(2.0f, acc)), ee);
}

__global__ __launch_bounds__(256)
void rescue_kernel(const float* __restrict__ emb) {
    const int q = (blockIdx.x * blockDim.x + threadIdx.x) >> 5;
    const int lane = threadIdx.x & 31;
    if (q >= N_PIX) return;
    const int cnt = g_ccount[q];
    const float zz = __ldg(&g_zn2[q]);
    unsigned long long best = 0xFFFFFFFFFFFFFFFFull;

    if (cnt <= MAXC) {
        unsigned long long abest = 0xFFFFFFFFFFFFFFFFull;
        for (int base = 0; base < cnt; base += 32) {
            int i = base + lane;
            if (i < cnt) {
                float s = g_cs[(size_t)q * MAXC + i];
                unsigned long long k =
                    ((unsigned long long)__float_as_uint(s) << 32) | (unsigned)g_ci[(size_t)q * MAXC + i];
                abest = min(abest, k);
            }
        }
#pragma unroll
        for (int o = 16; o; o >>= 1) abest = min(abest, __shfl_xor_sync(0xFFFFFFFFu, abest, o));
        const float thr = __uint_as_float((uint32_t)(abest >> 32)) + RESC_MARGIN;
        for (int base = 0; base < cnt; base += 32) {
            int i = base + lane;
            if (i < cnt && g_cs[(size_t)q * MAXC + i] <= thr) {
                int code = g_ci[(size_t)q * MAXC + i];
                float d = exact_score(q, code, emb, zz, __ldg(&g_en2[code]));
                unsigned long long k = ((unsigned long long)__float_as_uint(d) << 32) | (unsigned)code;
                best = min(best, k);
            }
        }
    } else {
        for (int j = lane; j < N_CODE; j += 32) {
            float d = exact_score(q, j, emb, zz, __ldg(&g_en2[j]));
            unsigned long long k = ((unsigned long long)__float_as_uint(d) << 32) | (unsigned)j;
            best = min(best, k);
        }
    }
#pragma unroll
    for (int o = 16; o; o >>= 1) best = min(best, __shfl_xor_sync(0xFFFFFFFFu, best, o));
    if (lane == 0) g_idx[q] = (int)(best & 0xFFFFFFFFull);
}

// ---------------- gather ----------------
__global__ __launch_bounds__(256)
void gather_kernel(const float* __restrict__ z, const float* __restrict__ emb,
                   float* __restrict__ out) {
    const int tx = threadIdx.x & 31;
    const int ty = threadIdx.x >> 5;
    const int p  = blockIdx.x * 32 + tx;
    const int idx = g_idx[p];
    const int n  = p >> 10;
    const int hw = p & 1023;
    const size_t base = (size_t)n * (CD * HWSZ) + hw;
    const float* erow = emb + (size_t)idx * CD;
#pragma unroll
    for (int cc = 0; cc < CD / 8; ++cc) {
        int c = cc * 8 + ty;
        float qv = __ldg(&erow[c]);
        size_t off = base + (size_t)c * HWSZ;
        out[off] = qv;
        float zv = z[off];
        out[OFF_ST + off] = __fadd_rn(zv, __fadd_rn(qv, -zv));
    }
    if (ty == 0) out[OFF_IDX + p] = (float)idx;
}

// ---------------------------------------------------------------------------
extern "C" void kernel_launch(void* const* d_in, const int* in_sizes, int n_in,
                              void* d_out, int out_size) {
    const float* z   = (const float*)d_in[0];
    const float* emb = (const float*)d_in[1];
    float* out = (float*)d_out;

    cudaFuncSetAttribute(gemm_cand_kernel, cudaFuncAttributeMaxDynamicSharedMemorySize, SMEM_TOTAL);

    transpose_z_kernel<<<dim3(32, 8, 16), dim3(32, 8)>>>(z);
    norms_kernel<<<N_PIX + N_CODE, 64>>>(emb);
    gemm_cand_kernel<<<dim3(N_CODE / 1024, N_PIX / 128), 256, SMEM_TOTAL>>>();
    rescue_kernel<<<(N_PIX * 32) / 256, 256>>>(emb);
    gather_kernel<<<N_PIX / 32, 256>>>(z, emb, out);
}

// round 8
// speedup vs baseline: 5.7168x; 1.0474x over previous
#include <cuda_runtime.h>
#include <cuda_bf16.h>
#include <cstdint>

// Problem constants
#define N_BATCH 16
#define CD      256
#define HWSZ    1024
#define N_PIX   (N_BATCH * HWSZ)   // 16384
#define N_CODE  8192

#define OFF_ST   (N_BATCH * CD * HWSZ)
#define OFF_IDX  (2 * N_BATCH * CD * HWSZ)

#define MAXC        256
#define CAND_MARGIN 6.0e-4f
#define RESC_MARGIN 4.0e-4f
#define PAIR_CAP    (N_PIX * MAXC)

// Scratch (device globals; no allocation allowed)
__device__ float              g_zt[N_PIX * CD];
__device__ __nv_bfloat16      g_abf[N_PIX * CD];
__device__ __nv_bfloat16      g_bbf[N_CODE * CD];
__device__ float              g_zn2[N_PIX];
__device__ float              g_en2[N_CODE];
__device__ int                g_ccount[N_PIX];
__device__ float              g_cs[N_PIX * MAXC];
__device__ int                g_ci[N_PIX * MAXC];
__device__ unsigned long long g_best[N_PIX];    // packed (d_bits<<32)|code
__device__ unsigned int       g_npairs;
__device__ int                g_pq[PAIR_CAP];
__device__ int                g_pc[PAIR_CAP];

// ---------------- helpers ----------------
__device__ __forceinline__ uint32_t smem_u32(const void* p) {
    uint32_t a;
    asm("{ .reg .u64 t; cvta.to.shared.u64 t, %1; cvt.u32.u64 %0, t; }" : "=r"(a) : "l"(p));
    return a;
}
__device__ __forceinline__ void cp16(uint32_t dst, const void* src) {
    asm volatile("cp.async.cg.shared.global [%0], [%1], 16;"
                 :: "r"(dst), "l"(__cvta_generic_to_global(src)));
}
__device__ __forceinline__ void cp_commit() { asm volatile("cp.async.commit_group;"); }
__device__ __forceinline__ void cp_wait0()  { asm volatile("cp.async.wait_group 0;"); }

__device__ __forceinline__ float score_chain(float zz, float m, float ee) {
    return __fadd_rn(__fadd_rn(zz, -__fmul_rn(2.0f, m)), ee);
}

// ---------------- prep: transpose + bf16 A ----------------
__global__ void transpose_z_kernel(const float* __restrict__ z) {
    __shared__ float tile[32][33];
    const int n = blockIdx.z, c0 = blockIdx.y * 32, p0 = blockIdx.x * 32;
    const int tx = threadIdx.x, ty = threadIdx.y;
#pragma unroll
    for (int i = 0; i < 4; ++i) {
        int c = c0 + ty + i * 8;
        tile[ty + i * 8][tx] = z[((size_t)(n * CD + c)) * HWSZ + p0 + tx];
    }
    __syncthreads();
#pragma unroll
    for (int i = 0; i < 4; ++i) {
        int p = p0 + ty + i * 8;
        size_t idx = ((size_t)(n * HWSZ + p)) * CD + c0 + tx;
        float v = tile[tx][ty + i * 8];
        g_zt[idx]  = v;
        g_abf[idx] = __float2bfloat16(v);
    }
}

// ---------------- prep: fused norms + B convert + state init ----------------
__global__ __launch_bounds__(64)
void norms_kernel(const float* __restrict__ emb) {
    __shared__ float buf[CD];
    const int r = blockIdx.x;
    const int tid = threadIdx.x;

    if (r == 0 && tid == 0) g_npairs = 0u;

    if (r < N_PIX) {
        const float4* src = (const float4*)(g_zt + (size_t)r * CD);
        ((float4*)buf)[tid] = __ldg(&src[tid]);
        if (tid == 0) { g_ccount[r] = 0; g_best[r] = 0xFFFFFFFFFFFFFFFFull; }
        __syncthreads();
        if (tid == 0) {
            float acc = 0.f;
#pragma unroll 16
            for (int k = 0; k < CD; ++k) {
                float v = buf[k];
                acc = __fadd_rn(acc, __fmul_rn(v, v));
            }
            g_zn2[r] = acc;
        }
    } else {
        const int j = r - N_PIX;
        const float4* src = (const float4*)(emb + (size_t)j * CD);
        float4 v = __ldg(&src[tid]);
        ((float4*)buf)[tid] = v;
        __nv_bfloat162* dst = (__nv_bfloat162*)(g_bbf + (size_t)j * CD);
        dst[tid * 2]     = __floats2bfloat162_rn(v.x, v.y);
        dst[tid * 2 + 1] = __floats2bfloat162_rn(v.z, v.w);
        __syncthreads();
        if (tid == 0) {
            float acc = 0.f;
#pragma unroll 16
            for (int k = 0; k < CD; ++k) {
                float w = buf[k];
                acc = __fadd_rn(acc, __fmul_rn(w, w));
            }
            g_en2[j] = acc;
        }
    }
}

// ---------------- GEMM (mma.sync bf16) + candidate collection ----------------
#define SMA_STRIDE 264
#define SMB_STRIDE 72
#define SM_A       0
#define SM_B0      (128 * SMA_STRIDE * 2)
#define SM_BSZ     (128 * SMB_STRIDE * 2)
#define SM_B1      (SM_B0 + SM_BSZ)
#define SM_RMIN    (SM_B1 + SM_BSZ)
#define SMEM_TOTAL (SM_RMIN + 512)

__global__ __launch_bounds__(256, 2)
void gemm_cand_kernel() {
    extern __shared__ char smem[];
    const uint32_t sb = smem_u32(smem);
    const int tid = threadIdx.x, lane = tid & 31, warp = tid >> 5;
    const int warpM = warp >> 2;
    const int warpN = warp & 3;
    const int m0 = blockIdx.y * 128;
    const int g0 = blockIdx.x * 1024;
    unsigned* rowminU = (unsigned*)(smem + SM_RMIN);

    {
        const __nv_bfloat16* Ab = g_abf + (size_t)m0 * CD;
#pragma unroll
        for (int i = 0; i < 16; ++i) {
            int g = i * 256 + tid, row = g >> 5, grp = g & 31;
            cp16(sb + SM_A + row * (SMA_STRIDE * 2) + grp * 16, Ab + (size_t)row * CD + grp * 8);
        }
        cp_commit();
    }
    if (tid < 128) rowminU[tid] = 0x7F7FFFFFu;

    float zz0[4], zz1[4];
#pragma unroll
    for (int ti = 0; ti < 4; ++ti) {
        int r = m0 + warpM * 64 + ti * 16 + (lane >> 2);
        zz0[ti] = __ldg(&g_zn2[r]);
        zz1[ti] = __ldg(&g_zn2[r + 8]);
    }

    auto loadB = [&](int nbase, int kc, int buf) {
        const __nv_bfloat16* Bb = g_bbf + (size_t)nbase * CD + kc * 64;
        uint32_t dst = sb + (buf ? SM_B1 : SM_B0);
#pragma unroll
        for (int i = 0; i < 4; ++i) {
            int g = i * 256 + tid, row = g >> 3, grp = g & 7;
            cp16(dst + row * (SMB_STRIDE * 2) + grp * 16, Bb + (size_t)row * CD + grp * 8);
        }
        cp_commit();
    };

    const uint32_t aAddrBase = sb + SM_A + (warpM * 64 + (lane & 15)) * (SMA_STRIDE * 2) + (lane >> 4) * 16;
    const uint32_t bRowOff   = (warpN * 32 + (lane & 7)) * (SMB_STRIDE * 2) + ((lane >> 3) & 1) * 16;

    loadB(g0, 0, 0);

    for (int nb = 0; nb < 8; ++nb) {
        const int n0 = g0 + nb * 128;
        float c[4][4][4];
#pragma unroll
        for (int ti = 0; ti < 4; ++ti)
#pragma unroll
            for (int tj = 0; tj < 4; ++tj)
#pragma unroll
                for (int d = 0; d < 4; ++d) c[ti][tj][d] = 0.f;

#pragma unroll 1
        for (int kc = 0; kc < 4; ++kc) {
            const int buf = kc & 1;
            cp_wait0();
            __syncthreads();
            if (kc < 3)      loadB(n0, kc + 1, buf ^ 1);
            else if (nb < 7) loadB(n0 + 128, 0, 0);
            const uint32_t bBase = sb + (buf ? SM_B1 : SM_B0) + bRowOff;
#pragma unroll
            for (int ks = 0; ks < 4; ++ks) {
                uint32_t a[4][4], b[4][2];
#pragma unroll
                for (int ti = 0; ti < 4; ++ti) {
                    uint32_t ad = aAddrBase + ti * 16 * (SMA_STRIDE * 2) + (kc * 64 + ks * 16) * 2;
                    asm volatile("ldmatrix.sync.aligned.m8n8.x4.shared.b16 {%0,%1,%2,%3}, [%4];"
                                 : "=r"(a[ti][0]), "=r"(a[ti][1]), "=r"(a[ti][2]), "=r"(a[ti][3])
                                 : "r"(ad));
                }
#pragma unroll
                for (int tj = 0; tj < 4; ++tj) {
                    uint32_t bd = bBase + tj * 8 * (SMB_STRIDE * 2) + (ks * 16) * 2;
                    asm volatile("ldmatrix.sync.aligned.m8n8.x2.shared.b16 {%0,%1}, [%2];"
                                 : "=r"(b[tj][0]), "=r"(b[tj][1]) : "r"(bd));
                }
#pragma unroll
                for (int ti = 0; ti < 4; ++ti)
#pragma unroll
                    for (int tj = 0; tj < 4; ++tj)
                        asm volatile(
                            "mma.sync.aligned.m16n8k16.row.col.f32.bf16.bf16.f32 "
                            "{%0,%1,%2,%3}, {%4,%5,%6,%7}, {%8,%9}, {%0,%1,%2,%3};"
                            : "+f"(c[ti][tj][0]), "+f"(c[ti][tj][1]),
                              "+f"(c[ti][tj][2]), "+f"(c[ti][tj][3])
                            : "r"(a[ti][0]), "r"(a[ti][1]), "r"(a[ti][2]), "r"(a[ti][3]),
                              "r"(b[tj][0]), "r"(b[tj][1]));
            }
        }

        float ee0[4], ee1[4];
#pragma unroll
        for (int tj = 0; tj < 4; ++tj) {
            int cidx = n0 + warpN * 32 + tj * 8 + 2 * (lane & 3);
            ee0[tj] = __ldg(&g_en2[cidx]);
            ee1[tj] = __ldg(&g_en2[cidx + 1]);
        }
#pragma unroll
        for (int ti = 0; ti < 4; ++ti) {
            float mn0 = 3.4e38f, mn1 = 3.4e38f;
#pragma unroll
            for (int tj = 0; tj < 4; ++tj) {
                float s0 = score_chain(zz0[ti], c[ti][tj][0], ee0[tj]);
                float s1 = score_chain(zz0[ti], c[ti][tj][1], ee1[tj]);
                float s2 = score_chain(zz1[ti], c[ti][tj][2], ee0[tj]);
                float s3 = score_chain(zz1[ti], c[ti][tj][3], ee1[tj]);
                c[ti][tj][0] = s0; c[ti][tj][1] = s1; c[ti][tj][2] = s2; c[ti][tj][3] = s3;
                mn0 = fminf(mn0, fminf(s0, s1));
                mn1 = fminf(mn1, fminf(s2, s3));
            }
            int r0 = warpM * 64 + ti * 16 + (lane >> 2);
            atomicMin(&rowminU[r0],     __float_as_uint(mn0));
            atomicMin(&rowminU[r0 + 8], __float_as_uint(mn1));
        }
        __syncthreads();
#pragma unroll
        for (int ti = 0; ti < 4; ++ti) {
            int r0 = warpM * 64 + ti * 16 + (lane >> 2);
            float t0 = __uint_as_float(rowminU[r0])     + CAND_MARGIN;
            float t1 = __uint_as_float(rowminU[r0 + 8]) + CAND_MARGIN;
            int q0 = m0 + r0, q1 = q0 + 8;
#pragma unroll
            for (int tj = 0; tj < 4; ++tj) {
                int cb = n0 + warpN * 32 + tj * 8 + 2 * (lane & 3);
                if (c[ti][tj][0] <= t0) {
                    int pos = atomicAdd(&g_ccount[q0], 1);
                    if (pos < MAXC) { g_cs[(size_t)q0 * MAXC + pos] = c[ti][tj][0]; g_ci[(size_t)q0 * MAXC + pos] = cb; }
                }
                if (c[ti][tj][1] <= t0) {
                    int pos = atomicAdd(&g_ccount[q0], 1);
                    if (pos < MAXC) { g_cs[(size_t)q0 * MAXC + pos] = c[ti][tj][1]; g_ci[(size_t)q0 * MAXC + pos] = cb + 1; }
                }
                if (c[ti][tj][2] <= t1) {
                    int pos = atomicAdd(&g_ccount[q1], 1);
                    if (pos < MAXC) { g_cs[(size_t)q1 * MAXC + pos] = c[ti][tj][2]; g_ci[(size_t)q1 * MAXC + pos] = cb; }
                }
                if (c[ti][tj][3] <= t1) {
                    int pos = atomicAdd(&g_ccount[q1], 1);
                    if (pos < MAXC) { g_cs[(size_t)q1 * MAXC + pos] = c[ti][tj][3]; g_ci[(size_t)q1 * MAXC + pos] = cb + 1; }
                }
            }
        }
        __syncthreads();
    }
}

// ---------------- rescue phase A: survivor compaction (warp per query) ------
__global__ __launch_bounds__(256)
void rescueA_kernel() {
    const int q = (blockIdx.x * blockDim.x + threadIdx.x) >> 5;
    const int lane = threadIdx.x & 31;
    if (q >= N_PIX) return;
    const int cnt = g_ccount[q];

    if (cnt > MAXC) {
        // overflow: exact-eval all codes (practically never taken)
        unsigned base;
        if (lane == 0) base = atomicAdd(&g_npairs, (unsigned)N_CODE);
        base = __shfl_sync(0xFFFFFFFFu, base, 0);
        for (int j = lane; j < N_CODE; j += 32) {
            g_pq[base + j] = q; g_pc[base + j] = j;
        }
        return;
    }

    // approx min over candidates
    unsigned long long abest = 0xFFFFFFFFFFFFFFFFull;
    for (int base = 0; base < cnt; base += 32) {
        int i = base + lane;
        if (i < cnt) {
            float s = g_cs[(size_t)q * MAXC + i];
            unsigned long long k =
                ((unsigned long long)__float_as_uint(s) << 32) | (unsigned)g_ci[(size_t)q * MAXC + i];
            abest = min(abest, k);
        }
    }
#pragma unroll
    for (int o = 16; o; o >>= 1) abest = min(abest, __shfl_xor_sync(0xFFFFFFFFu, abest, o));
    const float thr = __uint_as_float((uint32_t)(abest >> 32)) + RESC_MARGIN;

    // warp-aggregated emission of survivors
    for (int base = 0; base < cnt; base += 32) {
        int i = base + lane;
        bool pred = (i < cnt) && (g_cs[(size_t)q * MAXC + i] <= thr);
        unsigned mask = __ballot_sync(0xFFFFFFFFu, pred);
        if (!mask) continue;
        int leader = __ffs(mask) - 1;
        unsigned pbase = 0;
        if (lane == leader) pbase = atomicAdd(&g_npairs, (unsigned)__popc(mask));
        pbase = __shfl_sync(0xFFFFFFFFu, pbase, leader);
        if (pred) {
            unsigned off = pbase + __popc(mask & ((1u << lane) - 1u));
            g_pq[off] = q;
            g_pc[off] = g_ci[(size_t)q * MAXC + i];
        }
    }
}

// ---------------- rescue phase B: dense exact eval (thread per pair) --------
__global__ __launch_bounds__(256)
void rescueB_kernel(const float* __restrict__ emb) {
    const unsigned n = g_npairs;
    const unsigned stride = gridDim.x * blockDim.x;
    for (unsigned i = blockIdx.x * blockDim.x + threadIdx.x; i < n; i += stride) {
        const int q = g_pq[i];
        const int code = g_pc[i];
        const float4* zr = (const float4*)(g_zt + (size_t)q * CD);
        const float4* er = (const float4*)(emb + (size_t)code * CD);
        float acc = 0.f;
        // bit-exact: single accumulator, ascending k (float4 load, sequential FMAs)
#pragma unroll 8
        for (int k4 = 0; k4 < CD / 4; ++k4) {
            float4 a = __ldg(&zr[k4]);
            float4 b = __ldg(&er[k4]);
            acc = fmaf(a.x, b.x, acc);
            acc = fmaf(a.y, b.y, acc);
            acc = fmaf(a.z, b.z, acc);
            acc = fmaf(a.w, b.w, acc);
        }
        float d = __fadd_rn(__fadd_rn(__ldg(&g_zn2[q]), -__fmul_rn(2.0f, acc)), __ldg(&g_en2[code]));
        unsigned long long key = ((unsigned long long)__float_as_uint(d) << 32) | (unsigned)code;
        atomicMin(&g_best[q], key);
    }
}

// ---------------- gather ----------------
__global__ __launch_bounds__(256)
void gather_kernel(const float* __restrict__ z, const float* __restrict__ emb,
                   float* __restrict__ out) {
    const int tx = threadIdx.x & 31;
    const int ty = threadIdx.x >> 5;
    const int p  = blockIdx.x * 32 + tx;
    const int idx = (int)(g_best[p] & 0xFFFFFFFFull);
    const int n  = p >> 10;
    const int hw = p & 1023;
    const size_t base = (size_t)n * (CD * HWSZ) + hw;
    const float* erow = emb + (size_t)idx * CD;
#pragma unroll
    for (int cc = 0; cc < CD / 8; ++cc) {
        int c = cc * 8 + ty;
        float qv = __ldg(&erow[c]);
        size_t off = base + (size_t)c * HWSZ;
        out[off] = qv;
        float zv = z[off];
        out[OFF_ST + off] = __fadd_rn(zv, __fadd_rn(qv, -zv));
    }
    if (ty == 0) out[OFF_IDX + p] = (float)idx;
}

// ---------------------------------------------------------------------------
extern "C" void kernel_launch(void* const* d_in, const int* in_sizes, int n_in,
                              void* d_out, int out_size) {
    const float* z   = (const float*)d_in[0];
    const float* emb = (const float*)d_in[1];
    float* out = (float*)d_out;

    cudaFuncSetAttribute(gemm_cand_kernel, cudaFuncAttributeMaxDynamicSharedMemorySize, SMEM_TOTAL);

    transpose_z_kernel<<<dim3(32, 8, 16), dim3(32, 8)>>>(z);
    norms_kernel<<<N_PIX + N_CODE, 64>>>(emb);
    gemm_cand_kernel<<<dim3(N_CODE / 1024, N_PIX / 128), 256, SMEM_TOTAL>>>();
    rescueA_kernel<<<(N_PIX * 32) / 256, 256>>>();
    rescueB_kernel<<<512, 256>>>(emb);
    gather_kernel<<<N_PIX / 32, 256>>>(z, emb, out);
}